// round 11
// baseline (speedup 1.0000x reference)
#include <cuda_runtime.h>
#include <cuda_bf16.h>
#include <cstdint>

// ---- problem constants -----------------------------------------------------
#define MAX_NODES 2000000
#define MAX_LINKS 4000000

#define G_ACC   9.81f
#define RHO_I   917.0f
#define RHO_W   1000.0f
#define NU_W    1.787e-6f
#define OMEGA   1e-3f
#define L_HEAT  334000.0f
#define A_ICE   6e-24f
#define DT_STEP 0.01f

// ---- device scratch (static: allocation is forbidden) ----------------------
__device__ float2 g_sh[MAX_NODES];    // (conduit_size, hydraulic_head) packed
__device__ float2 g_link[MAX_LINKS];  // (discharge, dissipation) packed

// ---- kernel 1: pack node state (4 nodes / thread) --------------------------
__global__ __launch_bounds__(256) void pack_nodes(const float* __restrict__ S,
                                                  const float* __restrict__ h,
                                                  int n) {
    int j = blockIdx.x * blockDim.x + threadIdx.x;   // quad index
    int n4 = n >> 2;
    if (j < n4) {
        float4 s4 = __ldcs(reinterpret_cast<const float4*>(S) + j);
        float4 h4 = __ldcs(reinterpret_cast<const float4*>(h) + j);
        float4* dst = reinterpret_cast<float4*>(g_sh) + j * 2;
        dst[0] = make_float4(s4.x, h4.x, s4.y, h4.y);
        dst[1] = make_float4(s4.z, h4.z, s4.w, h4.w);
    }
    if (j == 0) {  // scalar tail
        for (int i = n4 << 2; i < n; i++) g_sh[i] = make_float2(S[i], h[i]);
    }
}

// ---- kernel 2: per-link discharge + dissipation (2 links / thread) ---------
__device__ __forceinline__ float2 link_math(float2 a, float2 b, float re, float len) {
    float s  = 0.5f * (a.x + b.x);
    float gh = (a.y - b.y) / len;
    float denom = 12.0f * NU_W * (1.0f + OMEGA * re);
    float T = (s * s * s) * G_ACC / denom;
    float q = T * gh;
    return make_float2(q, fabsf(q * gh));
}

__global__ __launch_bounds__(256) void link_pass(const float* __restrict__ reynolds,
                                                 const float* __restrict__ length,
                                                 const int*   __restrict__ head,
                                                 const int*   __restrict__ tail,
                                                 int n) {
    int j = blockIdx.x * blockDim.x + threadIdx.x;   // pair index
    int i = j * 2;
    if (i >= n) return;

    const float2* __restrict__ gsh = (const float2*)g_sh;

    if (i + 1 < n) {
        // one-shot streams: evict-first
        int2   hd = __ldcs(reinterpret_cast<const int2*>(head) + j);
        int2   tl = __ldcs(reinterpret_cast<const int2*>(tail) + j);
        float2 re = __ldcs(reinterpret_cast<const float2*>(reynolds) + j);
        float2 ln = __ldcs(reinterpret_cast<const float2*>(length) + j);

        // 4 independent random gathers in flight (L2-resident target)
        float2 a0 = __ldg(gsh + hd.x);
        float2 b0 = __ldg(gsh + tl.x);
        float2 a1 = __ldg(gsh + hd.y);
        float2 b1 = __ldg(gsh + tl.y);

        float2 r0 = link_math(a0, b0, re.x, ln.x);
        float2 r1 = link_math(a1, b1, re.y, ln.y);
        reinterpret_cast<float4*>(g_link)[j] = make_float4(r0.x, r0.y, r1.x, r1.y);
    } else {
        float2 a = __ldg(gsh + head[i]);
        float2 b = __ldg(gsh + tail[i]);
        g_link[i] = link_math(a, b, reynolds[i], length[i]);
    }
}

// ---- per-node physics ------------------------------------------------------
__device__ __forceinline__ void node_math(float fsum, float dsum, float area,
                                          float geo, float ice, float bed,
                                          float2 sh, float* s_new, float* flux) {
    *flux = fsum / area;
    float diss_node = RHO_W * G_ACC * (dsum * (1.0f / 6.0f));
    float melt_rate = (geo + diss_node) / L_HEAT;
    float melt_term = melt_rate * (1.0f / RHO_W - 1.0f / RHO_I);

    float overburden = RHO_I * G_ACC * ice;
    float wpress     = RHO_W * G_ACC * (sh.y - bed);
    float n_eff      = overburden - wpress;
    float creep      = A_ICE * n_eff * n_eff * n_eff;   // signed cube

    float s0 = sh.x;
    float k1 = melt_term - creep * s0;
    float k2 = melt_term - creep * (s0 + k1 * (DT_STEP * 0.5f));
    float k3 = melt_term - creep * (s0 + k2 * (DT_STEP * 0.5f));
    float k4 = melt_term - creep * (s0 + k3 * DT_STEP);
    *s_new = s0 + DT_STEP * (k1 + 2.0f * k2 + 2.0f * k3 + k4) * (1.0f / 6.0f);
}

// ---- kernel 3: per-node pass (2 nodes / thread, 2 gather batches of 6) -----
// MLP_p1 reduced 12 -> 6 to cut cross-CTA L1tex wavefront-queue contention
// (B300 spread model: spr grows with oe*MLP_p1 beyond ~16).
__global__ __launch_bounds__(256) void node_pass(const float* __restrict__ ice,
                                                 const float* __restrict__ bed,
                                                 const float* __restrict__ geo,
                                                 const float* __restrict__ area,
                                                 const int*   __restrict__ links,  // [N,6]
                                                 const int*   __restrict__ dirs,   // [N,6]
                                                 float*       __restrict__ out,    // [2,N]
                                                 int n) {
    int j = blockIdx.x * blockDim.x + threadIdx.x;   // node-pair index
    int i = j * 2;
    if (i >= n) return;

    const float2* __restrict__ glk = (const float2*)g_link;
    const float2* __restrict__ gsh = (const float2*)g_sh;

    if (i + 1 < n) {
        // 2 nodes = 12 ints = 3x int4, 16B-aligned (48B stride per pair)
        const int4* lp = reinterpret_cast<const int4*>(links) + j * 3;
        const int4* dp = reinterpret_cast<const int4*>(dirs)  + j * 3;
        int4 l0 = __ldcs(lp + 0), l1 = __ldcs(lp + 1), l2 = __ldcs(lp + 2);
        int4 d0 = __ldcs(dp + 0), d1 = __ldcs(dp + 1), d2 = __ldcs(dp + 2);

        // coalesced per-node streams (issued once, consumed later)
        float2 ar = __ldcs(reinterpret_cast<const float2*>(area) + j);
        float2 ge = __ldcs(reinterpret_cast<const float2*>(geo) + j);
        float2 ic = __ldcs(reinterpret_cast<const float2*>(ice) + j);
        float2 bd = __ldcs(reinterpret_cast<const float2*>(bed) + j);
        float4 sh4 = __ldg(reinterpret_cast<const float4*>(gsh) + j);  // L2-hot

        // ---- batch 1: node 0's 6 gathers, then its reduction ----
        float2 v0 = __ldg(glk + l0.x);
        float2 v1 = __ldg(glk + l0.y);
        float2 v2 = __ldg(glk + l0.z);
        float2 v3 = __ldg(glk + l0.w);
        float2 v4 = __ldg(glk + l1.x);
        float2 v5 = __ldg(glk + l1.y);

        float fsum0 = (float)d0.x * v0.x + (float)d0.y * v1.x + (float)d0.z * v2.x
                    + (float)d0.w * v3.x + (float)d1.x * v4.x + (float)d1.y * v5.x;
        float dsum0 = v0.y + v1.y + v2.y + v3.y + v4.y + v5.y;

        // ---- batch 2: node 1's 6 gathers, then its reduction ----
        float2 w0 = __ldg(glk + l1.z);
        float2 w1 = __ldg(glk + l1.w);
        float2 w2 = __ldg(glk + l2.x);
        float2 w3 = __ldg(glk + l2.y);
        float2 w4 = __ldg(glk + l2.z);
        float2 w5 = __ldg(glk + l2.w);

        float fsum1 = (float)d1.z * w0.x + (float)d1.w * w1.x + (float)d2.x * w2.x
                    + (float)d2.y * w3.x + (float)d2.z * w4.x + (float)d2.w * w5.x;
        float dsum1 = w0.y + w1.y + w2.y + w3.y + w4.y + w5.y;

        float sn0, fd0, sn1, fd1;
        node_math(fsum0, dsum0, ar.x, ge.x, ic.x, bd.x,
                  make_float2(sh4.x, sh4.y), &sn0, &fd0);
        node_math(fsum1, dsum1, ar.y, ge.y, ic.y, bd.y,
                  make_float2(sh4.z, sh4.w), &sn1, &fd1);

        __stcs(reinterpret_cast<float2*>(out) + j,     make_float2(sn0, sn1));
        __stcs(reinterpret_cast<float2*>(out + n) + j, make_float2(fd0, fd1));
    } else {
        // scalar tail (last node when n is odd)
        const int* lr = links + i * 6;
        const int* dr = dirs  + i * 6;
        float fsum = 0.0f, dsum = 0.0f;
        #pragma unroll
        for (int k = 0; k < 6; k++) {
            float2 v = __ldg(glk + lr[k]);
            fsum += (float)dr[k] * v.x;
            dsum += v.y;
        }
        float sn, fd;
        node_math(fsum, dsum, area[i], geo[i], ice[i], bed[i], gsh[i], &sn, &fd);
        out[i]     = sn;
        out[n + i] = fd;
    }
}

// ---- launch ----------------------------------------------------------------
extern "C" void kernel_launch(void* const* d_in, const int* in_sizes, int n_in,
                              void* d_out, int out_size) {
    const float* conduit_size = (const float*)d_in[0];
    const float* hydr_head    = (const float*)d_in[1];
    const float* reynolds     = (const float*)d_in[2];
    const float* ice_thick    = (const float*)d_in[3];
    const float* bedrock      = (const float*)d_in[4];
    const float* geo_flux     = (const float*)d_in[5];
    const float* link_len     = (const float*)d_in[6];
    const float* area_node    = (const float*)d_in[7];
    const int*   head         = (const int*)d_in[8];
    const int*   tail         = (const int*)d_in[9];
    const int*   links_at     = (const int*)d_in[10];
    const int*   dirs_at      = (const int*)d_in[11];
    float*       out          = (float*)d_out;

    int n_nodes = in_sizes[0];
    int n_links = in_sizes[2];

    const int TB = 256;
    int pack_thr = (n_nodes >> 2) + 1;            // quads + tail thread
    int link_thr = (n_links + 1) >> 1;            // pairs
    int node_thr = (n_nodes + 1) >> 1;            // pairs

    pack_nodes<<<(pack_thr + TB - 1) / TB, TB>>>(conduit_size, hydr_head, n_nodes);
    link_pass<<<(link_thr + TB - 1) / TB, TB>>>(reynolds, link_len, head, tail, n_links);
    node_pass<<<(node_thr + TB - 1) / TB, TB>>>(ice_thick, bedrock, geo_flux, area_node,
                                                links_at, dirs_at, out, n_nodes);
}

// round 12
// speedup vs baseline: 1.0159x; 1.0159x over previous
#include <cuda_runtime.h>
#include <cuda_bf16.h>
#include <cstdint>

// ---- problem constants -----------------------------------------------------
#define MAX_NODES 2000000
#define MAX_LINKS 4000000

#define G_ACC   9.81f
#define RHO_I   917.0f
#define RHO_W   1000.0f
#define NU_W    1.787e-6f
#define OMEGA   1e-3f
#define L_HEAT  334000.0f
#define A_ICE   6e-24f
#define DT_STEP 0.01f

// ---- device scratch (static: allocation is forbidden) ----------------------
__device__ float2 g_sh[MAX_NODES];    // (conduit_size, hydraulic_head) packed
__device__ float2 g_link[MAX_LINKS];  // (discharge, dissipation) packed

// ---- kernel 1: pack node state (2 nodes / thread) --------------------------
// Latency-limited kernel: more threads (3907 blocks vs 1954) shortens the
// single-wave critical path while keeping vectorized accesses.
__global__ __launch_bounds__(256) void pack_nodes(const float* __restrict__ S,
                                                  const float* __restrict__ h,
                                                  int n) {
    int j = blockIdx.x * blockDim.x + threadIdx.x;   // pair index
    int n2 = n >> 1;
    if (j < n2) {
        float2 s2 = __ldcs(reinterpret_cast<const float2*>(S) + j);
        float2 h2 = __ldcs(reinterpret_cast<const float2*>(h) + j);
        reinterpret_cast<float4*>(g_sh)[j] = make_float4(s2.x, h2.x, s2.y, h2.y);
    }
    if (j == 0 && (n & 1)) {  // scalar tail
        g_sh[n - 1] = make_float2(S[n - 1], h[n - 1]);
    }
}

// ---- kernel 2: per-link discharge + dissipation (2 links / thread) ---------
__device__ __forceinline__ float2 link_math(float2 a, float2 b, float re, float len) {
    float s  = 0.5f * (a.x + b.x);
    float gh = (a.y - b.y) / len;
    float denom = 12.0f * NU_W * (1.0f + OMEGA * re);
    float T = (s * s * s) * G_ACC / denom;
    float q = T * gh;
    return make_float2(q, fabsf(q * gh));
}

__global__ __launch_bounds__(256) void link_pass(const float* __restrict__ reynolds,
                                                 const float* __restrict__ length,
                                                 const int*   __restrict__ head,
                                                 const int*   __restrict__ tail,
                                                 int n) {
    int j = blockIdx.x * blockDim.x + threadIdx.x;   // pair index
    int i = j * 2;
    if (i >= n) return;

    const float2* __restrict__ gsh = (const float2*)g_sh;

    if (i + 1 < n) {
        // one-shot streams: evict-first
        int2   hd = __ldcs(reinterpret_cast<const int2*>(head) + j);
        int2   tl = __ldcs(reinterpret_cast<const int2*>(tail) + j);
        float2 re = __ldcs(reinterpret_cast<const float2*>(reynolds) + j);
        float2 ln = __ldcs(reinterpret_cast<const float2*>(length) + j);

        // 4 independent random gathers in flight (L2-resident target)
        float2 a0 = __ldg(gsh + hd.x);
        float2 b0 = __ldg(gsh + tl.x);
        float2 a1 = __ldg(gsh + hd.y);
        float2 b1 = __ldg(gsh + tl.y);

        float2 r0 = link_math(a0, b0, re.x, ln.x);
        float2 r1 = link_math(a1, b1, re.y, ln.y);
        reinterpret_cast<float4*>(g_link)[j] = make_float4(r0.x, r0.y, r1.x, r1.y);
    } else {
        float2 a = __ldg(gsh + head[i]);
        float2 b = __ldg(gsh + tail[i]);
        g_link[i] = link_math(a, b, reynolds[i], length[i]);
    }
}

// ---- per-node physics ------------------------------------------------------
__device__ __forceinline__ void node_math(float fsum, float dsum, float area,
                                          float geo, float ice, float bed,
                                          float2 sh, float* s_new, float* flux) {
    *flux = fsum / area;
    float diss_node = RHO_W * G_ACC * (dsum * (1.0f / 6.0f));
    float melt_rate = (geo + diss_node) / L_HEAT;
    float melt_term = melt_rate * (1.0f / RHO_W - 1.0f / RHO_I);

    float overburden = RHO_I * G_ACC * ice;
    float wpress     = RHO_W * G_ACC * (sh.y - bed);
    float n_eff      = overburden - wpress;
    float creep      = A_ICE * n_eff * n_eff * n_eff;   // signed cube

    float s0 = sh.x;
    float k1 = melt_term - creep * s0;
    float k2 = melt_term - creep * (s0 + k1 * (DT_STEP * 0.5f));
    float k3 = melt_term - creep * (s0 + k2 * (DT_STEP * 0.5f));
    float k4 = melt_term - creep * (s0 + k3 * DT_STEP);
    *s_new = s0 + DT_STEP * (k1 + 2.0f * k2 + 2.0f * k3 + k4) * (1.0f / 6.0f);
}

// ---- kernel 3: per-node pass (2 nodes / thread, 12 gathers upfront) --------
// R10 configuration — best measured (108.0us).
__global__ __launch_bounds__(256) void node_pass(const float* __restrict__ ice,
                                                 const float* __restrict__ bed,
                                                 const float* __restrict__ geo,
                                                 const float* __restrict__ area,
                                                 const int*   __restrict__ links,  // [N,6]
                                                 const int*   __restrict__ dirs,   // [N,6]
                                                 float*       __restrict__ out,    // [2,N]
                                                 int n) {
    int j = blockIdx.x * blockDim.x + threadIdx.x;   // node-pair index
    int i = j * 2;
    if (i >= n) return;

    const float2* __restrict__ glk = (const float2*)g_link;
    const float2* __restrict__ gsh = (const float2*)g_sh;

    if (i + 1 < n) {
        // 2 nodes = 12 ints = 3x int4, 16B-aligned (48B stride per pair)
        const int4* lp = reinterpret_cast<const int4*>(links) + j * 3;
        const int4* dp = reinterpret_cast<const int4*>(dirs)  + j * 3;
        int4 l0 = __ldcs(lp + 0), l1 = __ldcs(lp + 1), l2 = __ldcs(lp + 2);
        int4 d0 = __ldcs(dp + 0), d1 = __ldcs(dp + 1), d2 = __ldcs(dp + 2);

        // 12 independent random gathers in flight
        float2 v0  = __ldg(glk + l0.x);
        float2 v1  = __ldg(glk + l0.y);
        float2 v2  = __ldg(glk + l0.z);
        float2 v3  = __ldg(glk + l0.w);
        float2 v4  = __ldg(glk + l1.x);
        float2 v5  = __ldg(glk + l1.y);
        float2 v6  = __ldg(glk + l1.z);
        float2 v7  = __ldg(glk + l1.w);
        float2 v8  = __ldg(glk + l2.x);
        float2 v9  = __ldg(glk + l2.y);
        float2 v10 = __ldg(glk + l2.z);
        float2 v11 = __ldg(glk + l2.w);

        float2 ar = __ldcs(reinterpret_cast<const float2*>(area) + j);
        float2 ge = __ldcs(reinterpret_cast<const float2*>(geo) + j);
        float2 ic = __ldcs(reinterpret_cast<const float2*>(ice) + j);
        float2 bd = __ldcs(reinterpret_cast<const float2*>(bed) + j);
        float4 sh4 = __ldg(reinterpret_cast<const float4*>(gsh) + j);  // L2-hot

        float fsum0 = (float)d0.x * v0.x + (float)d0.y * v1.x + (float)d0.z * v2.x
                    + (float)d0.w * v3.x + (float)d1.x * v4.x + (float)d1.y * v5.x;
        float dsum0 = v0.y + v1.y + v2.y + v3.y + v4.y + v5.y;
        float fsum1 = (float)d1.z * v6.x + (float)d1.w * v7.x + (float)d2.x * v8.x
                    + (float)d2.y * v9.x + (float)d2.z * v10.x + (float)d2.w * v11.x;
        float dsum1 = v6.y + v7.y + v8.y + v9.y + v10.y + v11.y;

        float sn0, fd0, sn1, fd1;
        node_math(fsum0, dsum0, ar.x, ge.x, ic.x, bd.x,
                  make_float2(sh4.x, sh4.y), &sn0, &fd0);
        node_math(fsum1, dsum1, ar.y, ge.y, ic.y, bd.y,
                  make_float2(sh4.z, sh4.w), &sn1, &fd1);

        __stcs(reinterpret_cast<float2*>(out) + j,     make_float2(sn0, sn1));
        __stcs(reinterpret_cast<float2*>(out + n) + j, make_float2(fd0, fd1));
    } else {
        // scalar tail (last node when n is odd)
        const int* lr = links + i * 6;
        const int* dr = dirs  + i * 6;
        float fsum = 0.0f, dsum = 0.0f;
        #pragma unroll
        for (int k = 0; k < 6; k++) {
            float2 v = __ldg(glk + lr[k]);
            fsum += (float)dr[k] * v.x;
            dsum += v.y;
        }
        float sn, fd;
        node_math(fsum, dsum, area[i], geo[i], ice[i], bed[i], gsh[i], &sn, &fd);
        out[i]     = sn;
        out[n + i] = fd;
    }
}

// ---- launch ----------------------------------------------------------------
extern "C" void kernel_launch(void* const* d_in, const int* in_sizes, int n_in,
                              void* d_out, int out_size) {
    const float* conduit_size = (const float*)d_in[0];
    const float* hydr_head    = (const float*)d_in[1];
    const float* reynolds     = (const float*)d_in[2];
    const float* ice_thick    = (const float*)d_in[3];
    const float* bedrock      = (const float*)d_in[4];
    const float* geo_flux     = (const float*)d_in[5];
    const float* link_len     = (const float*)d_in[6];
    const float* area_node    = (const float*)d_in[7];
    const int*   head         = (const int*)d_in[8];
    const int*   tail         = (const int*)d_in[9];
    const int*   links_at     = (const int*)d_in[10];
    const int*   dirs_at      = (const int*)d_in[11];
    float*       out          = (float*)d_out;

    int n_nodes = in_sizes[0];
    int n_links = in_sizes[2];

    const int TB = 256;
    int pack_thr = (n_nodes + 1) >> 1;            // node pairs
    int link_thr = (n_links + 1) >> 1;            // link pairs
    int node_thr = (n_nodes + 1) >> 1;            // node pairs

    pack_nodes<<<(pack_thr + TB - 1) / TB, TB>>>(conduit_size, hydr_head, n_nodes);
    link_pass<<<(link_thr + TB - 1) / TB, TB>>>(reynolds, link_len, head, tail, n_links);
    node_pass<<<(node_thr + TB - 1) / TB, TB>>>(ice_thick, bedrock, geo_flux, area_node,
                                                links_at, dirs_at, out, n_nodes);
}